// round 5
// baseline (speedup 1.0000x reference)
#include <cuda_runtime.h>
#include <cuda_bf16.h>
#include <cstdint>
#include <math.h>

// ---------------- problem constants ----------------
#define BB 4
#define TT 1024
#define EE 768
#define HH 12
#define LL 4
#define VV 50257
#define HDIM 64
#define NROWS (BB*TT)          // 4096

// ---------------- scratch (device globals; no allocation allowed) ----------
__device__ float g_x  [NROWS*EE];
__device__ float g_xn [NROWS*EE];
__device__ float g_qkv[NROWS*3*EE];
__device__ float g_att[(size_t)BB*HH*TT*TT];     // 201 MB
__device__ float g_vT [(size_t)BB*HH*HDIM*TT];
__device__ float g_y  [NROWS*EE];
__device__ float g_h  [NROWS*4*EE];
__device__ float g_nll[NROWS];
__device__ float g_vld[NROWS];

// ---------------- GEMM (NT: A[M,K] row-major, B[N,K] row-major, C=A*B^T) ----
// fp32 emulated via bf16x3: x = hi + lo (bf16 each); C += Ah*Bh + Ah*Bl + Al*Bh
#define BM 128
#define BN 128
#define BKK 32
#define KW  (BKK/2)            // 16 bf16x2 words per row
#define PADW 20                // words per smem row -> conflict-free frag LDS
#define STW (BM*PADW)          // 2560 words per tile stage
// smem word regions: Ah[2 stages] Al Bh Bl
#define OFF_AH 0
#define OFF_AL (2*STW)
#define OFF_BH (4*STW)
#define OFF_BL (6*STW)
#define SMEM_WORDS (8*STW)     // 20480 words = 81920 B

__device__ __forceinline__ uint32_t pk2(__nv_bfloat16 a, __nv_bfloat16 b){
    __nv_bfloat162 t = __halves2bfloat162(a, b);
    return *reinterpret_cast<uint32_t*>(&t);
}

// split float4 (elements k..k+3) into hi/lo bf16x2 words at word index widx, widx+1
__device__ __forceinline__ void split_store(uint32_t* sw, int bh, int bl, int widx, float4 v){
    __nv_bfloat16 h0 = __float2bfloat16_rn(v.x);
    __nv_bfloat16 h1 = __float2bfloat16_rn(v.y);
    __nv_bfloat16 h2 = __float2bfloat16_rn(v.z);
    __nv_bfloat16 h3 = __float2bfloat16_rn(v.w);
    __nv_bfloat16 l0 = __float2bfloat16_rn(v.x - __bfloat162float(h0));
    __nv_bfloat16 l1 = __float2bfloat16_rn(v.y - __bfloat162float(h1));
    __nv_bfloat16 l2 = __float2bfloat16_rn(v.z - __bfloat162float(h2));
    __nv_bfloat16 l3 = __float2bfloat16_rn(v.w - __bfloat162float(h3));
    sw[bh + widx]     = pk2(h0, h1);
    sw[bh + widx + 1] = pk2(h2, h3);
    sw[bl + widx]     = pk2(l0, l1);
    sw[bl + widx + 1] = pk2(l2, l3);
}

#define MMA_BF16(Cc, A0,A1,A2,A3, B0,B1)                                     \
    asm volatile("mma.sync.aligned.m16n8k16.row.col.f32.bf16.bf16.f32 "      \
        "{%0,%1,%2,%3}, {%4,%5,%6,%7}, {%8,%9}, {%0,%1,%2,%3};\n"            \
        : "+f"(Cc[0]), "+f"(Cc[1]), "+f"(Cc[2]), "+f"(Cc[3])                 \
        : "r"(A0), "r"(A1), "r"(A2), "r"(A3), "r"(B0), "r"(B1));

// MODE: 0 = (+bias?) store          1 = +bias, exact GELU
//       2 = +bias + residual        3 = *scale, causal mask, skip upper blocks
//       4 = plain store, K trimmed to diagonal (AV)
template<int MODE>
__global__ void __launch_bounds__(256)
gemm_nt(const float* __restrict__ A, long sAo, long sAi, int lda,
        const float* __restrict__ Bmat, long sBo, long sBi, int ldb,
        float* __restrict__ C, long sCo, long sCi, int ldc,
        const float* __restrict__ bias,
        const float* __restrict__ Res, int ldr,
        int M, int N, int K, int innerCnt, float scale)
{
    int bn = blockIdx.x, bm = blockIdx.y, bz = blockIdx.z;
    if (MODE == 3 && bn > bm) return;       // causal: whole block above diagonal
    int zo = bz / innerCnt, zi = bz - zo*innerCnt;
    A    += zo*sAo + zi*sAi;
    Bmat += zo*sBo + zi*sBi;
    C    += zo*sCo + zi*sCi;

    extern __shared__ uint32_t sw[];

    int Keff = (MODE == 4) ? min(K, (bm+1)*BM) : K;
    int KT = Keff / BKK;

    int tid = threadIdx.x;
    const float* Ab = A    + (long)bm*BM*lda;
    const float* Bb = Bmat + (long)bn*BN*ldb;
    int nbase = bn*BN;

    int lr[4], lk[4];
    #pragma unroll
    for (int i=0;i<4;i++){ int id = tid + i*256; lr[i] = id>>3; lk[i] = (id&7)*4; }

    // prologue: tile 0 -> stage 0
    {
        #pragma unroll
        for (int i=0;i<4;i++){
            float4 v = *(const float4*)(Ab + (long)lr[i]*lda + lk[i]);
            split_store(sw, OFF_AH, OFF_AL, lr[i]*PADW + (lk[i]>>1), v);
        }
        #pragma unroll
        for (int i=0;i<4;i++){
            float4 v = make_float4(0.f,0.f,0.f,0.f);
            if (nbase + lr[i] < N) v = *(const float4*)(Bb + (long)lr[i]*ldb + lk[i]);
            split_store(sw, OFF_BH, OFF_BL, lr[i]*PADW + (lk[i]>>1), v);
        }
    }

    float c[4][4][4];
    #pragma unroll
    for (int i=0;i<4;i++)
        #pragma unroll
        for (int j=0;j<4;j++){ c[i][j][0]=0.f;c[i][j][1]=0.f;c[i][j][2]=0.f;c[i][j][3]=0.f; }

    int lane = tid & 31, wid = tid >> 5;
    int wm = (wid >> 2) * 64;   // warp grid 2 x 4, warp tile 64x32
    int wn = (wid & 3) * 32;
    int gq = lane >> 2, tg = lane & 3;

    int cur = 0;
    for (int kt = 0; kt < KT; kt++){
        __syncthreads();                 // stage `cur` ready for everyone

        // prefetch next tile to registers (latency hides under the MMA section)
        float4 na[4], nb[4];
        if (kt+1 < KT){
            int k0 = (kt+1)*BKK;
            #pragma unroll
            for (int i=0;i<4;i++)
                na[i] = *(const float4*)(Ab + (long)lr[i]*lda + k0 + lk[i]);
            #pragma unroll
            for (int i=0;i<4;i++){
                nb[i] = make_float4(0.f,0.f,0.f,0.f);
                if (nbase + lr[i] < N)
                    nb[i] = *(const float4*)(Bb + (long)lr[i]*ldb + k0 + lk[i]);
            }
        }

        int ah_base = OFF_AH + cur*STW, al_base = OFF_AL + cur*STW;
        int bh_base = OFF_BH + cur*STW, bl_base = OFF_BL + cur*STW;
        #pragma unroll
        for (int ks = 0; ks < 2; ks++){
            int kc = ks*8 + tg;
            uint32_t ah[4][4], bh[4][2];
            #pragma unroll
            for (int i=0;i<4;i++){
                int r = wm + i*16 + gq;
                ah[i][0] = sw[ah_base + r*PADW + kc];
                ah[i][1] = sw[ah_base + (r+8)*PADW + kc];
                ah[i][2] = sw[ah_base + r*PADW + kc + 4];
                ah[i][3] = sw[ah_base + (r+8)*PADW + kc + 4];
            }
            #pragma unroll
            for (int j=0;j<4;j++){
                int n = wn + j*8 + gq;
                bh[j][0] = sw[bh_base + n*PADW + kc];
                bh[j][1] = sw[bh_base + n*PADW + kc + 4];
            }
            #pragma unroll
            for (int i=0;i<4;i++)
                #pragma unroll
                for (int j=0;j<4;j++)
                    MMA_BF16(c[i][j], ah[i][0],ah[i][1],ah[i][2],ah[i][3], bh[j][0],bh[j][1]);

            uint32_t bl[4][2];
            #pragma unroll
            for (int j=0;j<4;j++){
                int n = wn + j*8 + gq;
                bl[j][0] = sw[bl_base + n*PADW + kc];
                bl[j][1] = sw[bl_base + n*PADW + kc + 4];
            }
            #pragma unroll
            for (int i=0;i<4;i++)
                #pragma unroll
                for (int j=0;j<4;j++)
                    MMA_BF16(c[i][j], ah[i][0],ah[i][1],ah[i][2],ah[i][3], bl[j][0],bl[j][1]);

            uint32_t al[4][4];
            #pragma unroll
            for (int i=0;i<4;i++){
                int r = wm + i*16 + gq;
                al[i][0] = sw[al_base + r*PADW + kc];
                al[i][1] = sw[al_base + (r+8)*PADW + kc];
                al[i][2] = sw[al_base + r*PADW + kc + 4];
                al[i][3] = sw[al_base + (r+8)*PADW + kc + 4];
            }
            #pragma unroll
            for (int i=0;i<4;i++)
                #pragma unroll
                for (int j=0;j<4;j++)
                    MMA_BF16(c[i][j], al[i][0],al[i][1],al[i][2],al[i][3], bh[j][0],bh[j][1]);
        }

        // store prefetched tile into the other stage (safe: other threads only
        // read stage `cur` this iteration; next iteration's reads are after sync)
        if (kt+1 < KT){
            int nst = cur ^ 1;
            int ah2 = OFF_AH + nst*STW, al2 = OFF_AL + nst*STW;
            int bh2 = OFF_BH + nst*STW, bl2 = OFF_BL + nst*STW;
            #pragma unroll
            for (int i=0;i<4;i++)
                split_store(sw, ah2, al2, lr[i]*PADW + (lk[i]>>1), na[i]);
            #pragma unroll
            for (int i=0;i<4;i++)
                split_store(sw, bh2, bl2, lr[i]*PADW + (lk[i]>>1), nb[i]);
        }
        cur ^= 1;
    }

    // epilogue
    #pragma unroll
    for (int i=0;i<4;i++){
        int r0 = bm*BM + wm + i*16 + gq;
        #pragma unroll
        for (int j=0;j<4;j++){
            int c0 = nbase + wn + j*8 + tg*2;
            #pragma unroll
            for (int h2=0; h2<2; h2++){
                int rr = r0 + h2*8;
                #pragma unroll
                for (int cc=0; cc<2; cc++){
                    int col = c0 + cc;
                    if (col >= N) continue;
                    float v = c[i][j][h2*2 + cc];
                    if (MODE == 0){ if (bias) v += bias[col]; }
                    else if (MODE == 1){ v += bias[col];
                        v = 0.5f*v*(1.f + erff(v*0.70710678118654752f)); }
                    else if (MODE == 2){ v += bias[col] + Res[(long)rr*ldr + col]; }
                    else if (MODE == 3){ v *= scale; if (col > rr) v = -1e30f; }
                    C[(long)rr*ldc + col] = v;
                }
            }
        }
    }
}

// ---------------- embedding ----------------
__global__ void embed_k(const int* __restrict__ idx, const float* __restrict__ wte,
                        const float* __restrict__ wpe, float* __restrict__ x)
{
    int i = blockIdx.x*256 + threadIdx.x;
    if (i >= NROWS*EE) return;
    int row = i / EE, col = i - row*EE;
    int t = row & (TT-1);
    x[i] = wte[(long)idx[row]*EE + col] + wpe[(long)t*EE + col];
}

// ---------------- layernorm (1 block / row) ----------------
__global__ void layernorm_k(const float* __restrict__ x, const float* __restrict__ w,
                            const float* __restrict__ b, float* __restrict__ o)
{
    int row = blockIdx.x;
    const float* xr = x + (long)row*EE;
    float* orow = o + (long)row*EE;
    int tid = threadIdx.x;
    float v0 = xr[tid], v1 = xr[tid+256], v2 = xr[tid+512];
    float s = v0+v1+v2;
    float q = v0*v0+v1*v1+v2*v2;
    __shared__ float sh1[256], sh2[256];
    sh1[tid]=s; sh2[tid]=q; __syncthreads();
    #pragma unroll
    for (int off=128; off>0; off>>=1){
        if (tid < off){ sh1[tid]+=sh1[tid+off]; sh2[tid]+=sh2[tid+off]; }
        __syncthreads();
    }
    float mean = sh1[0]*(1.f/EE);
    float var  = sh2[0]*(1.f/EE) - mean*mean;
    float rstd = rsqrtf(var + 1e-5f);
    orow[tid]     = (v0-mean)*rstd*w[tid]     + b[tid];
    orow[tid+256] = (v1-mean)*rstd*w[tid+256] + b[tid+256];
    orow[tid+512] = (v2-mean)*rstd*w[tid+512] + b[tid+512];
}

// ---------------- V transpose: qkv -> vT[z][d][k] ----------------
__global__ void transpose_v(const float* __restrict__ qkv, float* __restrict__ vT)
{
    int z = blockIdx.y; int b = z/HH, h = z - b*HH;
    int k0 = blockIdx.x * 64;
    __shared__ float t[64][65];
    const float* src = qkv + ((long)(b*TT + k0))*(3*EE) + 2*EE + h*HDIM;
    int tid = threadIdx.x;
    #pragma unroll
    for (int i=0;i<16;i++){
        int id = tid + i*256;
        int kr = id >> 6, d = id & 63;
        t[kr][d] = src[(long)kr*(3*EE) + d];
    }
    __syncthreads();
    float* dst = vT + (long)z*HDIM*TT + k0;
    #pragma unroll
    for (int i=0;i<16;i++){
        int id = tid + i*256;
        int d = id >> 6, kc = id & 63;
        dst[(long)d*TT + kc] = t[kc][d];
    }
}

// ---------------- causal row softmax (values live in registers) ----------------
__global__ void softmax_causal(float* __restrict__ att)
{
    int rid = blockIdx.x;
    int z = rid >> 10, q = rid & (TT-1);
    float* p = att + (long)z*TT*TT + (long)q*TT;
    int kend = ((q >> 7) + 1) << 7;      // diagonal block end (mult of 128)
    int tid = threadIdx.x;
    float v[4];
    float m = -1e30f;
    #pragma unroll
    for (int i=0;i<4;i++){
        int k = tid + i*256;
        v[i] = (k < kend) ? p[k] : -1e30f;
        m = fmaxf(m, v[i]);
    }
    __shared__ float sh[256];
    sh[tid] = m; __syncthreads();
    #pragma unroll
    for (int off=128; off>0; off>>=1){
        if (tid < off) sh[tid] = fmaxf(sh[tid], sh[tid+off]);
        __syncthreads();
    }
    m = sh[0]; __syncthreads();
    float s = 0.f;
    #pragma unroll
    for (int i=0;i<4;i++){ v[i] = __expf(v[i] - m); s += v[i]; }
    sh[tid] = s; __syncthreads();
    #pragma unroll
    for (int off=128; off>0; off>>=1){
        if (tid < off) sh[tid] += sh[tid+off];
        __syncthreads();
    }
    float inv = 1.f / sh[0];
    #pragma unroll
    for (int i=0;i<4;i++){
        int k = tid + i*256;
        if (k < kend) p[k] = v[i]*inv;
    }
}

// ---------------- loss: online logsumexp per row (single logits read) --------
__global__ void loss_rows(const float* __restrict__ lg, const int* __restrict__ tgt,
                          float* __restrict__ nll, float* __restrict__ vld)
{
    long row = blockIdx.x;
    const float* p = lg + row*(long)VV;
    int tid = threadIdx.x;
    float m = -3.0e38f, s = 0.f;
    for (int k = tid; k < VV; k += 256){
        float x = p[k];
        if (x > m){ s = s*__expf(m - x) + 1.f; m = x; }
        else s += __expf(x - m);
    }
    __shared__ float sm[256], ss[256];
    sm[tid]=m; ss[tid]=s; __syncthreads();
    #pragma unroll
    for (int off=128; off>0; off>>=1){
        if (tid < off){
            float m2 = sm[tid+off], s2 = ss[tid+off];
            float mm = fmaxf(sm[tid], m2);
            ss[tid] = ss[tid]*__expf(sm[tid]-mm) + s2*__expf(m2-mm);
            sm[tid] = mm;
        }
        __syncthreads();
    }
    if (tid == 0){
        float lse = sm[0] + logf(ss[0]);
        int t = tgt[row];
        if (t != -1){ nll[row] = lse - p[t]; vld[row] = 1.f; }
        else        { nll[row] = 0.f;       vld[row] = 0.f; }
    }
}

__global__ void loss_final(const float* __restrict__ nll, const float* __restrict__ vld,
                           float* __restrict__ out)
{
    int tid = threadIdx.x;
    float a = 0.f, b = 0.f;
    for (int i = tid; i < NROWS; i += 256){ a += nll[i]; b += vld[i]; }
    __shared__ float s1[256], s2[256];
    s1[tid]=a; s2[tid]=b; __syncthreads();
    #pragma unroll
    for (int off=128; off>0; off>>=1){
        if (tid < off){ s1[tid]+=s1[tid+off]; s2[tid]+=s2[tid+off]; }
        __syncthreads();
    }
    if (tid == 0) out[0] = s1[0] / fmaxf(s2[0], 1.f);
}

// ---------------- host ----------------
extern "C" void kernel_launch(void* const* d_in, const int* in_sizes, int n_in,
                              void* d_out, int out_size)
{
    const int*   idx       = (const int*)  d_in[0];
    const int*   tgt       = (const int*)  d_in[1];
    const float* wte       = (const float*)d_in[2];
    const float* wpe       = (const float*)d_in[3];
    const float* ln1_w     = (const float*)d_in[4];
    const float* ln1_b     = (const float*)d_in[5];
    const float* attn_w    = (const float*)d_in[6];
    const float* attn_b    = (const float*)d_in[7];
    const float* aproj_w   = (const float*)d_in[8];
    const float* aproj_b   = (const float*)d_in[9];
    const float* ln2_w     = (const float*)d_in[10];
    const float* ln2_b     = (const float*)d_in[11];
    const float* fc_w      = (const float*)d_in[12];
    const float* fc_b      = (const float*)d_in[13];
    const float* proj_w    = (const float*)d_in[14];
    const float* proj_b    = (const float*)d_in[15];
    const float* lnf_w     = (const float*)d_in[16];
    const float* lnf_b     = (const float*)d_in[17];
    float* out = (float*)d_out;

    float *x, *xn, *qkv, *att, *vT, *y, *hb, *nll, *vld;
    cudaGetSymbolAddress((void**)&x,   g_x);
    cudaGetSymbolAddress((void**)&xn,  g_xn);
    cudaGetSymbolAddress((void**)&qkv, g_qkv);
    cudaGetSymbolAddress((void**)&att, g_att);
    cudaGetSymbolAddress((void**)&vT,  g_vT);
    cudaGetSymbolAddress((void**)&y,   g_y);
    cudaGetSymbolAddress((void**)&hb,  g_h);
    cudaGetSymbolAddress((void**)&nll, g_nll);
    cudaGetSymbolAddress((void**)&vld, g_vld);

    const size_t smemSz = (size_t)SMEM_WORDS*sizeof(uint32_t);   // 81920 B
    cudaFuncSetAttribute(gemm_nt<0>, cudaFuncAttributeMaxDynamicSharedMemorySize, (int)smemSz);
    cudaFuncSetAttribute(gemm_nt<1>, cudaFuncAttributeMaxDynamicSharedMemorySize, (int)smemSz);
    cudaFuncSetAttribute(gemm_nt<2>, cudaFuncAttributeMaxDynamicSharedMemorySize, (int)smemSz);
    cudaFuncSetAttribute(gemm_nt<3>, cudaFuncAttributeMaxDynamicSharedMemorySize, (int)smemSz);
    cudaFuncSetAttribute(gemm_nt<4>, cudaFuncAttributeMaxDynamicSharedMemorySize, (int)smemSz);

    embed_k<<<(NROWS*EE + 255)/256, 256>>>(idx, wte, wpe, x);

    for (int l = 0; l < LL; l++){
        layernorm_k<<<NROWS, 256>>>(x, ln1_w + l*EE, ln1_b + l*EE, xn);

        // QKV: [4096,2304] = xn @ attn_w[l]^T + b
        gemm_nt<0><<<dim3(3*EE/BN, NROWS/BM, 1), 256, smemSz>>>(
            xn, 0, 0, EE,
            attn_w + (long)l*3*EE*EE, 0, 0, EE,
            qkv, 0, 0, 3*EE,
            attn_b + (long)l*3*EE, nullptr, 0,
            NROWS, 3*EE, EE, 1, 1.f);

        transpose_v<<<dim3(TT/64, BB*HH), 256>>>(qkv, vT);

        // scores = Q K^T / 8 (causal, batched over 48 (b,h))
        gemm_nt<3><<<dim3(TT/BN, TT/BM, BB*HH), 256, smemSz>>>(
            qkv,       (long)TT*3*EE, HDIM, 3*EE,
            qkv + EE,  (long)TT*3*EE, HDIM, 3*EE,
            att, (long)HH*TT*TT, (long)TT*TT, TT,
            nullptr, nullptr, 0,
            TT, TT, HDIM, HH, 0.125f);

        softmax_causal<<<BB*HH*TT, 256>>>(att);

        // y = att @ V   (K trimmed to diagonal block)
        gemm_nt<4><<<dim3(1, TT/BM, BB*HH), 256, smemSz>>>(
            att, (long)HH*TT*TT, (long)TT*TT, TT,
            vT,  (long)HH*HDIM*TT, (long)HDIM*TT, TT,
            y,   (long)TT*EE, HDIM, EE,
            nullptr, nullptr, 0,
            TT, HDIM, TT, HH, 1.f);

        // x = x + y @ aproj^T + b
        gemm_nt<2><<<dim3(EE/BN, NROWS/BM, 1), 256, smemSz>>>(
            y, 0, 0, EE,
            aproj_w + (long)l*EE*EE, 0, 0, EE,
            x, 0, 0, EE,
            aproj_b + (long)l*EE, x, EE,
            NROWS, EE, EE, 1, 1.f);

        layernorm_k<<<NROWS, 256>>>(x, ln2_w + l*EE, ln2_b + l*EE, xn);

        // h = gelu(xn @ fc^T + b)
        gemm_nt<1><<<dim3(4*EE/BN, NROWS/BM, 1), 256, smemSz>>>(
            xn, 0, 0, EE,
            fc_w + (long)l*4*EE*EE, 0, 0, EE,
            hb, 0, 0, 4*EE,
            fc_b + (long)l*4*EE, nullptr, 0,
            NROWS, 4*EE, EE, 1, 1.f);

        // x = x + h @ proj^T + b
        gemm_nt<2><<<dim3(EE/BN, NROWS/BM, 1), 256, smemSz>>>(
            hb, 0, 0, 4*EE,
            proj_w + (long)l*EE*4*EE, 0, 0, 4*EE,
            x, 0, 0, EE,
            proj_b + (long)l*EE, x, EE,
            NROWS, EE, 4*EE, 1, 1.f);
    }

    layernorm_k<<<NROWS, 256>>>(x, lnf_w, lnf_b, xn);

    // logits = xn @ wte^T  -> d_out
    gemm_nt<0><<<dim3((VV + BN - 1)/BN, NROWS/BM, 1), 256, smemSz>>>(
        xn, 0, 0, EE,
        wte, 0, 0, EE,
        out, 0, 0, VV,
        nullptr, nullptr, 0,
        NROWS, VV, EE, 1, 1.f);

    long BTV = (long)NROWS * VV;
    if ((long)out_size > BTV){
        loss_rows<<<NROWS, 256>>>(out, tgt, nll, vld);
        loss_final<<<1, 256>>>(nll, vld, out + BTV);
    }
}